// round 15
// baseline (speedup 1.0000x reference)
#include <cuda_runtime.h>
#include <cuda_bf16.h>
#include <stdint.h>

// ---------------------------------------------------------------------------
// Constants
// ---------------------------------------------------------------------------
#define MRR_A 0.987f
#define MRR_R 0.99f

#define OUT_CH 256
#define IN_CH  128
#define HW     56
#define HWP    58          // padded spatial
#define HWSQ   3136
#define KTOT   1152
#define PIXTOT 200704

#define KC      64
#define NCHUNK  18         // 9 (r,s) positions x 2 channel-halves
#define MT      128
#define NT      128
#define STAGES  3
#define NTHREADS 512       // 16 warps, grid 4x4, warp tile 32x32
#define NWARPS  16

// per-stage smem layout (bytes): A hi/lo + B hi (B lo comes from gmem table)
#define STG_BYTES 49152
#define SOFF_AHI  0        // 128 rows x 128B = 16KB
#define SOFF_ALO  16384
#define SOFF_BHI  32768    // 128 rows x 128B = 16KB
#define OFF_SCALE (STAGES * STG_BYTES)          // 147456
#define OFF_BIAS  (OFF_SCALE + 512)
#define OFF_MBAR  (OFF_BIAS + 512)              // full[0..2] @ +0,8,16; free[0..2] @ +24,32,40
#define SMEM_TOTAL (OFF_MBAR + 64)              // ~148.5KB

// ---------------------------------------------------------------------------
// Device-global scratch (zero-initialized -> halo stays zero forever)
// ---------------------------------------------------------------------------
__device__ __align__(256) __nv_bfloat16 g_x_hi[64 * HWP * HWP * IN_CH];
__device__ __align__(256) __nv_bfloat16 g_x_lo[64 * HWP * HWP * IN_CH];
__device__ __align__(256) __nv_bfloat16 g_w_hi[OUT_CH * KTOT];   // [oc][rs][c]
// B-lo fragments in mma-register order:
// idx = (((kc*8 + band)*4 + ks)*4 + j)*32 + lane ; uint2 = {lo r0, lo r1}
__device__ __align__(256) uint2 g_w_lof[18 * 8 * 4 * 4 * 32];    // 0.56 MB
__device__ float g_scale[OUT_CH];
__device__ float g_bias[OUT_CH];

// ---------------------------------------------------------------------------
// Helpers
// ---------------------------------------------------------------------------
__device__ __forceinline__ uint32_t smem_u32(const void* p) {
    uint32_t a;
    asm("{ .reg .u64 t; cvta.to.shared.u64 t, %1; cvt.u32.u64 %0, t; }" : "=r"(a) : "l"(p));
    return a;
}
__device__ __forceinline__ uint32_t sw128(uint32_t off) {
    return off ^ ((off >> 3) & 0x70);
}
__device__ __forceinline__ void cp16(uint32_t dst, const __nv_bfloat16* src) {
    asm volatile("cp.async.cg.shared.global [%0], [%1], 16;"
                 :: "r"(dst), "l"(__cvta_generic_to_global(src)));
}

#define MBAR_INIT(a, c) \
    asm volatile("mbarrier.init.shared.b64 [%0], %1;" :: "r"(a), "r"(c) : "memory")
#define CP_MBAR_ARRIVE(a) \
    asm volatile("cp.async.mbarrier.arrive.noinc.shared.b64 [%0];" :: "r"(a) : "memory")
#define MBAR_ARRIVE(a) \
    asm volatile("mbarrier.arrive.shared.b64 _, [%0];" :: "r"(a) : "memory")

#define MBAR_WAIT(mbar, parity) do {                                              \
    uint32_t _m = (uint32_t)(mbar);                                               \
    uint32_t _p = (uint32_t)(parity);                                             \
    uint32_t _done;                                                               \
    asm volatile(                                                                 \
        "{\n\t.reg .pred p;\n\t"                                                  \
        "mbarrier.try_wait.parity.acquire.cta.shared::cta.b64 p, [%1], %2;\n\t"   \
        "selp.b32 %0, 1, 0, p;\n\t}"                                              \
        : "=r"(_done) : "r"(_m), "r"(_p) : "memory");                             \
    if (!_done) {                                                                 \
        asm volatile(                                                             \
            "{\n\t.reg .pred P1;\n\t"                                             \
            "WAIT_LOOP_%=:\n\t"                                                   \
            "mbarrier.try_wait.parity.acquire.cta.shared::cta.b64 P1, [%0], %1, 0x989680;\n\t" \
            "@P1 bra.uni WAIT_DONE_%=;\n\t"                                       \
            "bra.uni WAIT_LOOP_%=;\n\t"                                           \
            "WAIT_DONE_%=:\n\t}"                                                  \
            :: "r"(_m), "r"(_p) : "memory");                                      \
    }                                                                             \
} while (0)

__device__ __forceinline__ void ldsm4(uint32_t* r, uint32_t addr) {
    asm volatile("ldmatrix.sync.aligned.m8n8.x4.shared.b16 {%0,%1,%2,%3}, [%4];"
                 : "=r"(r[0]), "=r"(r[1]), "=r"(r[2]), "=r"(r[3]) : "r"(addr));
}
__device__ __forceinline__ void mma16816(float* d, const uint32_t* a, const uint32_t* b) {
    asm volatile(
        "mma.sync.aligned.m16n8k16.row.col.f32.bf16.bf16.f32 "
        "{%0,%1,%2,%3}, {%4,%5,%6,%7}, {%8,%9}, {%0,%1,%2,%3};"
        : "+f"(d[0]), "+f"(d[1]), "+f"(d[2]), "+f"(d[3])
        : "r"(a[0]), "r"(a[1]), "r"(a[2]), "r"(a[3]), "r"(b[0]), "r"(b[1]));
}

__device__ __forceinline__ float mrr_tr(float phi) {
    float cc = cosf(phi);
    float ar = MRR_A * MRR_R;
    float num = MRR_A * MRR_A - 2.0f * ar * cc + MRR_R * MRR_R;
    float den = 1.0f - 2.0f * ar * cc + ar * ar;
    return num / den;
}

// ---------------------------------------------------------------------------
// Kernel 1: weights — g_w_hi in [oc][rs][c] order + g_w_lof fragment table
// ---------------------------------------------------------------------------
__global__ void prep_kernel(const float* __restrict__ phase,
                            const float* __restrict__ gamma,
                            const float* __restrict__ beta,
                            const float* __restrict__ rmean,
                            const float* __restrict__ rvar) {
    int idx = blockIdx.x * 256 + threadIdx.x;
    if (idx < OUT_CH * KTOT) {
        int oc  = idx / KTOT;
        int kp  = idx - oc * KTOT;     // rs*128 + c
        int rs  = kp >> 7;
        int c   = kp & 127;
        int korig = c * 9 + rs;
        int gy = oc >> 3, i = oc & 7;
        int gx = korig >> 3, j = korig & 7;
        float tr = mrr_tr(phase[((gy * 144 + gx) * 8 + i) * 8 + j]);
        g_w_hi[idx] = __float2bfloat16(tr);
    }
    if (idx < 18 * 8 * 4 * 4 * 32) {   // B-lo fragment table
        int lane = idx & 31;
        int j    = (idx >> 5) & 3;
        int ks   = (idx >> 7) & 3;
        int band = (idx >> 9) & 7;
        int kc   = idx >> 12;
        int half = kc & 1, rs = kc >> 1;
        int oc   = band * 32 + j * 8 + (lane >> 2);
        int gy = oc >> 3, i = oc & 7;
        uint32_t w[2];
        #pragma unroll
        for (int r = 0; r < 2; ++r) {
            uint32_t pk = 0;
            #pragma unroll
            for (int e = 0; e < 2; ++e) {
                int c = half * 64 + ks * 16 + (lane & 3) * 2 + r * 8 + e;
                int korig = c * 9 + rs;
                int gx = korig >> 3, jj = korig & 7;
                float tr = mrr_tr(phase[((gy * 144 + gx) * 8 + i) * 8 + jj]);
                __nv_bfloat16 hi = __float2bfloat16(tr);
                __nv_bfloat16 lo = __float2bfloat16(tr - __bfloat162float(hi));
                pk |= (uint32_t)__bfloat16_as_ushort(lo) << (e * 16);
            }
            w[r] = pk;
        }
        g_w_lof[idx] = make_uint2(w[0], w[1]);
    }
    if (idx < OUT_CH) {
        float inv = gamma[idx] * rsqrtf(rvar[idx] + 1e-5f);
        g_scale[idx] = inv;
        g_bias[idx]  = beta[idx] - rmean[idx] * inv;
    }
}

// ---------------------------------------------------------------------------
// Kernel 2: x NCHW fp32 -> padded NHWC bf16 hi/lo (smem transpose)
// ---------------------------------------------------------------------------
__global__ void __launch_bounds__(256)
xprep_kernel(const float* __restrict__ x) {
    __shared__ float tile[IN_CH][HW + 1];
    const int n = blockIdx.x, h = blockIdx.y;
    const int tid = threadIdx.x;
    const float* xb = x + (size_t)n * IN_CH * HWSQ + h * HW;
    #pragma unroll 4
    for (int i = tid; i < IN_CH * HW; i += 256) {
        int c = i / HW, w = i - c * HW;
        tile[c][w] = xb[(size_t)c * HWSQ + w];
    }
    __syncthreads();
    const size_t obase = (((size_t)n * HWP + h + 1) * HWP + 1) * IN_CH;
    #pragma unroll 4
    for (int i = tid; i < HW * IN_CH; i += 256) {
        int w = i >> 7, c = i & 127;
        float v = tile[c][w];
        __nv_bfloat16 hi = __float2bfloat16(v);
        g_x_hi[obase + (size_t)w * IN_CH + c] = hi;
        g_x_lo[obase + (size_t)w * IN_CH + c] = __float2bfloat16(v - __bfloat162float(hi));
    }
}

// ---------------------------------------------------------------------------
// Kernel 3: implicit-GEMM conv. A hi/lo + B hi via smem ring, B lo via LDG
//   fragment table. bf16x3 mma.sync. 512 threads, 4x4 warps of 32x32,
//   3-stage mbarrier pipeline with cross-chunk fragment prefetch (R10 flow).
// ---------------------------------------------------------------------------
__global__ void __launch_bounds__(NTHREADS, 1)
conv_kernel(float* __restrict__ out) {
    extern __shared__ char smem[];
    const uint32_t sb = smem_u32(smem);
    const uint32_t mb = sb + OFF_MBAR;
    const int tid = threadIdx.x;
    const int wid = tid >> 5;
    const int lid = tid & 31;
    const int p0  = blockIdx.y * MT;   // pixel tile base
    const int oc0 = blockIdx.x * NT;   // oc tile base (adjacent bids share A in L2)

    const int warpM = wid >> 2;        // 0..3 -> 32-pixel band
    const int warpN = wid & 3;         // 0..3 -> 32-oc band
    const int bband = (oc0 >> 5) + warpN;   // global 32-oc band 0..7

    if (tid == 0) {
        #pragma unroll
        for (int s = 0; s < STAGES; ++s) {
            MBAR_INIT(mb + s * 8, NTHREADS);        // full[s]: per-thread cp arrivals
            MBAR_INIT(mb + 24 + s * 8, NWARPS);     // free[s]: per-warp arrivals
        }
    }
    if (tid < NT) {
        ((float*)(smem + OFF_SCALE))[tid] = g_scale[oc0 + tid];
        ((float*)(smem + OFF_BIAS))[tid]  = g_bias[oc0 + tid];
    }
    __syncthreads();   // init visibility; only CTA-wide barrier

    // ---- loaders -----------------------------------------------------------
    // A: 4 threads per 128B pixel row, 2 segs each (hi and lo) -> 4 cp16
    const int arow  = tid >> 2;                // 0..127
    const int asegb = (tid & 3) * 2;           // seg start (of 8)
    // B hi: 4 threads per 128B oc row, 2 segs each -> 2 cp16
    const int brow  = tid >> 2;                // 0..127
    const int bsegb = (tid & 3) * 2;

    const int pg   = p0 + arow;
    const int nimg = pg / HWSQ;
    const int rem  = pg - nimg * HWSQ;
    const int oh   = rem / HW;
    const int ow   = rem - oh * HW;
    const __nv_bfloat16* xhi_n = g_x_hi + (size_t)nimg * (HWP * HWP * IN_CH);
    const __nv_bfloat16* xlo_n = g_x_lo + (size_t)nimg * (HWP * HWP * IN_CH);
    uint32_t dA[2], dB[2];
    #pragma unroll
    for (int j = 0; j < 2; ++j) {
        dA[j] = sw128((uint32_t)(arow * 128 + (asegb + j) * 16));
        dB[j] = sw128((uint32_t)(brow * 128 + (bsegb + j) * 16));
    }

    auto issue_loads = [&](int kc, int st) {
        const int rs = kc >> 1, half = kc & 1;
        const int r = rs / 3, sc = rs - r * 3;
        const size_t aoff = (((size_t)(oh + r) * HWP) + (ow + sc)) * IN_CH
                            + half * 64 + asegb * 8;
        const size_t boff = ((size_t)(oc0 + brow) * 9 + rs) * 128
                            + half * 64 + bsegb * 8;
        const uint32_t s0 = sb + st * STG_BYTES;
        #pragma unroll
        for (int j = 0; j < 2; ++j) {
            cp16(s0 + SOFF_AHI + dA[j], xhi_n + aoff + j * 8);
            cp16(s0 + SOFF_ALO + dA[j], xlo_n + aoff + j * 8);
            cp16(s0 + SOFF_BHI + dB[j], g_w_hi + boff + j * 8);
        }
    };

    float acc[2][4][4];
    #pragma unroll
    for (int f = 0; f < 2; ++f)
        #pragma unroll
        for (int g = 0; g < 4; ++g)
            #pragma unroll
            for (int e = 0; e < 4; ++e) acc[f][g][e] = 0.0f;

    // ldmatrix lane mapping
    const int li = lid >> 3;
    const int lj = lid & 7;
    const int a_row = warpM * 32 + (li & 1) * 8 + lj;
    const int a_kof = (li >> 1) * 8;
    const int b_row = warpN * 32 + (li >> 1) * 8 + lj;
    const int b_kof = (li & 1) * 8;

    // double-buffered fragments
    uint32_t Ahi[2][2][4], Alo[2][2][4], Bhi[2][4][2], Blo[2][4][2];

    // load fragments for one ks: A hi/lo + B hi from stage smem, B lo from gmem
    auto load_frags = [&](int kc, uint32_t s0, int ks, int bu) {
        // B lo first: longest latency (L2)
        {
            const uint2* wl = g_w_lof + ((((kc * 8 + bband) * 4 + ks) * 4) << 5) + lid;
            #pragma unroll
            for (int j = 0; j < 4; ++j) {
                uint2 v = __ldg(wl + j * 32);
                Blo[bu][j][0] = v.x; Blo[bu][j][1] = v.y;
            }
        }
        #pragma unroll
        for (int h = 0; h < 2; ++h) {
            uint32_t off = sw128((uint32_t)((b_row + h * 16) * 128 +
                                            (ks * 16 + b_kof) * 2));
            uint32_t t[4];
            ldsm4(t, s0 + SOFF_BHI + off);
            Bhi[bu][h*2+0][0] = t[0]; Bhi[bu][h*2+0][1] = t[1];
            Bhi[bu][h*2+1][0] = t[2]; Bhi[bu][h*2+1][1] = t[3];
        }
        #pragma unroll
        for (int f = 0; f < 2; ++f) {
            uint32_t off = sw128((uint32_t)((a_row + f * 16) * 128 +
                                            (ks * 16 + a_kof) * 2));
            ldsm4(Ahi[bu][f], s0 + SOFF_AHI + off);
            ldsm4(Alo[bu][f], s0 + SOFF_ALO + off);
        }
    };

    auto mma_block = [&](int bu) {
        #pragma unroll
        for (int f = 0; f < 2; ++f)
            #pragma unroll
            for (int g = 0; g < 4; ++g) {
                mma16816(acc[f][g], Ahi[bu][f], Bhi[bu][g]);
                mma16816(acc[f][g], Ahi[bu][f], Blo[bu][g]);
                mma16816(acc[f][g], Alo[bu][f], Bhi[bu][g]);
            }
    };

    // ---- prologue: fill stages 0,1; preload chunk0 ks0 frags ---------------
    issue_loads(0, 0); CP_MBAR_ARRIVE(mb + 0);
    issue_loads(1, 1); CP_MBAR_ARRIVE(mb + 8);
    MBAR_WAIT(mb + 0, 0);
    load_frags(0, sb, 0, 0);

    for (int kc = 0; kc < NCHUNK; ++kc) {
        const int rnd = kc / 3;
        const int s   = kc - rnd * 3;
        const uint32_t s0 = sb + s * STG_BYTES;

        // ks = 0
        load_frags(kc, s0, 1, 1);
        mma_block(0);
        // ks = 1
        load_frags(kc, s0, 2, 0);
        mma_block(1);
        // ks = 2: last stage-s reads -> release stage early (warp-counted)
        load_frags(kc, s0, 3, 1);
        if (lid == 0) MBAR_ARRIVE(mb + 24 + s * 8);
        mma_block(0);
        // ks = 3: cross-chunk prefetch (next chunk's ks0 from next stage)
        if (kc + 1 < NCHUNK) {
            const int rn1 = (kc + 1) / 3;
            const int sn1 = (kc + 1) - rn1 * 3;
            MBAR_WAIT(mb + sn1 * 8, rn1 & 1);            // usually already fired
            load_frags(kc + 1, sb + sn1 * STG_BYTES, 0, 0);
        }
        mma_block(1);

        // refill: stage (kc+2)%3 with chunk kc+2
        const int kn = kc + 2;
        if (kn < NCHUNK) {
            const int rn = kn / 3;
            const int sn = kn - rn * 3;
            if (kn >= STAGES)
                MBAR_WAIT(mb + 24 + sn * 8, (rn - 1) & 1);
            issue_loads(kn, sn);
            CP_MBAR_ARRIVE(mb + sn * 8);
        }
    }

    // ---- epilogue: BN + ReLU6 + stores ------------------------------------
    const float* ss = (const float*)(smem + OFF_SCALE);
    const float* bb = (const float*)(smem + OFF_BIAS);

    #pragma unroll
    for (int f = 0; f < 2; ++f) {
        int p1 = p0 + warpM * 32 + f * 16 + (lid >> 2);
        int p2 = p1 + 8;
        int n1 = p1 / HWSQ, r1 = p1 - n1 * HWSQ;
        int n2 = p2 / HWSQ, r2 = p2 - n2 * HWSQ;
        float* o1 = out + (size_t)n1 * OUT_CH * HWSQ + r1;
        float* o2 = out + (size_t)n2 * OUT_CH * HWSQ + r2;
        #pragma unroll
        for (int g = 0; g < 4; ++g) {
            int cl = warpN * 32 + g * 8 + (lid & 3) * 2;
            int ocA = oc0 + cl, ocB = ocA + 1;
            float sA = ss[cl], bA = bb[cl];
            float sB = ss[cl + 1], bB = bb[cl + 1];
            float v0 = fminf(fmaxf(acc[f][g][0] * sA + bA, 0.0f), 6.0f);
            float v1 = fminf(fmaxf(acc[f][g][1] * sB + bB, 0.0f), 6.0f);
            float v2 = fminf(fmaxf(acc[f][g][2] * sA + bA, 0.0f), 6.0f);
            float v3 = fminf(fmaxf(acc[f][g][3] * sB + bB, 0.0f), 6.0f);
            o1[(size_t)ocA * HWSQ] = v0;
            o1[(size_t)ocB * HWSQ] = v1;
            o2[(size_t)ocA * HWSQ] = v2;
            o2[(size_t)ocB * HWSQ] = v3;
        }
    }
}

// ---------------------------------------------------------------------------
// Launch
// ---------------------------------------------------------------------------
extern "C" void kernel_launch(void* const* d_in, const int* in_sizes, int n_in,
                              void* d_out, int out_size) {
    const float* x     = (const float*)d_in[0];
    const float* phase = (const float*)d_in[1];
    const float* gamma = (const float*)d_in[2];
    const float* beta  = (const float*)d_in[3];
    const float* rmean = (const float*)d_in[4];
    const float* rvar  = (const float*)d_in[5];
    float* out = (float*)d_out;

    cudaFuncSetAttribute(conv_kernel,
                         cudaFuncAttributeMaxDynamicSharedMemorySize, SMEM_TOTAL);

    prep_kernel<<<(OUT_CH * KTOT + 255) / 256, 256>>>(phase, gamma, beta, rmean, rvar);
    dim3 xg(64, HW);
    xprep_kernel<<<xg, 256>>>(x);

    dim3 grid(OUT_CH / NT, PIXTOT / MT);   // (2, 1568): oc-major for A-tile L2 reuse
    conv_kernel<<<grid, NTHREADS, SMEM_TOTAL>>>(out);
}

// round 16
// speedup vs baseline: 1.4428x; 1.4428x over previous
#include <cuda_runtime.h>
#include <cuda_fp16.h>
#include <stdint.h>

// ---------------------------------------------------------------------------
// Constants
// ---------------------------------------------------------------------------
#define MRR_A 0.987f
#define MRR_R 0.99f

#define OUT_CH 256
#define IN_CH  128
#define HW     56
#define HWP    58          // padded spatial
#define HWSQ   3136
#define KTOT   1152
#define PIXTOT 200704

#define KC      64
#define NCHUNK  18         // 9 (r,s) positions x 2 channel-halves
#define MT      128
#define NT      128
#define STAGES  3
#define NTHREADS 512       // 16 warps, grid 4x4, warp tile 32x32
#define NWARPS  16

// per-stage smem layout (bytes): A hi/lo + B (all fp16)
#define STG_BYTES 49152
#define SOFF_AHI  0        // 128 rows x 128B = 16KB
#define SOFF_ALO  16384
#define SOFF_B    32768    // 128 rows x 128B = 16KB
#define OFF_SCALE (STAGES * STG_BYTES)          // 147456
#define OFF_BIAS  (OFF_SCALE + 512)
#define OFF_MBAR  (OFF_BIAS + 512)              // full[0..2] @ +0,8,16; free[0..2] @ +24,32,40
#define SMEM_TOTAL (OFF_MBAR + 64)              // ~148.5KB

// ---------------------------------------------------------------------------
// Device-global scratch (zero-initialized -> halo stays zero forever)
// ---------------------------------------------------------------------------
__device__ __align__(256) __half g_x_hi[64 * HWP * HWP * IN_CH];
__device__ __align__(256) __half g_x_lo[64 * HWP * HWP * IN_CH];
__device__ __align__(256) __half g_w[OUT_CH * KTOT];   // [oc][rs][c], single fp16
__device__ float g_scale[OUT_CH];
__device__ float g_bias[OUT_CH];

// ---------------------------------------------------------------------------
// Helpers
// ---------------------------------------------------------------------------
__device__ __forceinline__ uint32_t smem_u32(const void* p) {
    uint32_t a;
    asm("{ .reg .u64 t; cvta.to.shared.u64 t, %1; cvt.u32.u64 %0, t; }" : "=r"(a) : "l"(p));
    return a;
}
__device__ __forceinline__ uint32_t sw128(uint32_t off) {
    return off ^ ((off >> 3) & 0x70);
}
__device__ __forceinline__ void cp16(uint32_t dst, const __half* src) {
    asm volatile("cp.async.cg.shared.global [%0], [%1], 16;"
                 :: "r"(dst), "l"(__cvta_generic_to_global(src)));
}

#define MBAR_INIT(a, c) \
    asm volatile("mbarrier.init.shared.b64 [%0], %1;" :: "r"(a), "r"(c) : "memory")
#define CP_MBAR_ARRIVE(a) \
    asm volatile("cp.async.mbarrier.arrive.noinc.shared.b64 [%0];" :: "r"(a) : "memory")
#define MBAR_ARRIVE(a) \
    asm volatile("mbarrier.arrive.shared.b64 _, [%0];" :: "r"(a) : "memory")

#define MBAR_WAIT(mbar, parity) do {                                              \
    uint32_t _m = (uint32_t)(mbar);                                               \
    uint32_t _p = (uint32_t)(parity);                                             \
    uint32_t _done;                                                               \
    asm volatile(                                                                 \
        "{\n\t.reg .pred p;\n\t"                                                  \
        "mbarrier.try_wait.parity.acquire.cta.shared::cta.b64 p, [%1], %2;\n\t"   \
        "selp.b32 %0, 1, 0, p;\n\t}"                                              \
        : "=r"(_done) : "r"(_m), "r"(_p) : "memory");                             \
    if (!_done) {                                                                 \
        asm volatile(                                                             \
            "{\n\t.reg .pred P1;\n\t"                                             \
            "WAIT_LOOP_%=:\n\t"                                                   \
            "mbarrier.try_wait.parity.acquire.cta.shared::cta.b64 P1, [%0], %1, 0x989680;\n\t" \
            "@P1 bra.uni WAIT_DONE_%=;\n\t"                                       \
            "bra.uni WAIT_LOOP_%=;\n\t"                                           \
            "WAIT_DONE_%=:\n\t}"                                                  \
            :: "r"(_m), "r"(_p) : "memory");                                      \
    }                                                                             \
} while (0)

__device__ __forceinline__ void ldsm4(uint32_t* r, uint32_t addr) {
    asm volatile("ldmatrix.sync.aligned.m8n8.x4.shared.b16 {%0,%1,%2,%3}, [%4];"
                 : "=r"(r[0]), "=r"(r[1]), "=r"(r[2]), "=r"(r[3]) : "r"(addr));
}
__device__ __forceinline__ void mma16816(float* d, const uint32_t* a, const uint32_t* b) {
    asm volatile(
        "mma.sync.aligned.m16n8k16.row.col.f32.f16.f16.f32 "
        "{%0,%1,%2,%3}, {%4,%5,%6,%7}, {%8,%9}, {%0,%1,%2,%3};"
        : "+f"(d[0]), "+f"(d[1]), "+f"(d[2]), "+f"(d[3])
        : "r"(a[0]), "r"(a[1]), "r"(a[2]), "r"(a[3]), "r"(b[0]), "r"(b[1]));
}

__device__ __forceinline__ float mrr_tr(float phi) {
    float cc = cosf(phi);
    float ar = MRR_A * MRR_R;
    float num = MRR_A * MRR_A - 2.0f * ar * cc + MRR_R * MRR_R;
    float den = 1.0f - 2.0f * ar * cc + ar * ar;
    return num / den;
}

// ---------------------------------------------------------------------------
// Kernel 1: weights — MRR phase -> fp16 in [oc][rs][c] order + BN fold
// ---------------------------------------------------------------------------
__global__ void prep_kernel(const float* __restrict__ phase,
                            const float* __restrict__ gamma,
                            const float* __restrict__ beta,
                            const float* __restrict__ rmean,
                            const float* __restrict__ rvar) {
    int idx = blockIdx.x * 256 + threadIdx.x;
    if (idx < OUT_CH * KTOT) {
        int oc  = idx / KTOT;
        int kp  = idx - oc * KTOT;     // rs*128 + c
        int rs  = kp >> 7;
        int c   = kp & 127;
        int korig = c * 9 + rs;        // original (c,r,s) K order used by the blocks
        int gy = oc >> 3, i = oc & 7;
        int gx = korig >> 3, j = korig & 7;
        float tr = mrr_tr(phase[((gy * 144 + gx) * 8 + i) * 8 + j]);
        g_w[idx] = __float2half(tr);
    }
    if (idx < OUT_CH) {
        float inv = gamma[idx] * rsqrtf(rvar[idx] + 1e-5f);
        g_scale[idx] = inv;
        g_bias[idx]  = beta[idx] - rmean[idx] * inv;
    }
}

// ---------------------------------------------------------------------------
// Kernel 2: x NCHW fp32 -> padded NHWC fp16 hi/lo (smem transpose)
// ---------------------------------------------------------------------------
__global__ void __launch_bounds__(256)
xprep_kernel(const float* __restrict__ x) {
    __shared__ float tile[IN_CH][HW + 1];
    const int n = blockIdx.x, h = blockIdx.y;
    const int tid = threadIdx.x;
    const float* xb = x + (size_t)n * IN_CH * HWSQ + h * HW;
    #pragma unroll 4
    for (int i = tid; i < IN_CH * HW; i += 256) {
        int c = i / HW, w = i - c * HW;
        tile[c][w] = xb[(size_t)c * HWSQ + w];
    }
    __syncthreads();
    const size_t obase = (((size_t)n * HWP + h + 1) * HWP + 1) * IN_CH;
    #pragma unroll 4
    for (int i = tid; i < HW * IN_CH; i += 256) {
        int w = i >> 7, c = i & 127;
        float v = tile[c][w];
        __half hi = __float2half(v);
        g_x_hi[obase + (size_t)w * IN_CH + c] = hi;
        g_x_lo[obase + (size_t)w * IN_CH + c] = __float2half(v - __half2float(hi));
    }
}

// ---------------------------------------------------------------------------
// Kernel 3: implicit-GEMM conv, mbarrier 3-stage pipeline, fp16x2 mma.sync
//   512 threads, warp grid 4x4, warp tile 32x32, cross-chunk fragment pipeline
// ---------------------------------------------------------------------------
__global__ void __launch_bounds__(NTHREADS, 1)
conv_kernel(float* __restrict__ out) {
    extern __shared__ char smem[];
    const uint32_t sb = smem_u32(smem);
    const uint32_t mb = sb + OFF_MBAR;
    const int tid = threadIdx.x;
    const int wid = tid >> 5;
    const int lid = tid & 31;
    const int p0  = blockIdx.y * MT;   // pixel tile base
    const int oc0 = blockIdx.x * NT;   // oc tile base (adjacent bids share A in L2)

    const int warpM = wid >> 2;        // 0..3 -> 32-pixel band
    const int warpN = wid & 3;         // 0..3 -> 32-oc band

    if (tid == 0) {
        #pragma unroll
        for (int s = 0; s < STAGES; ++s) {
            MBAR_INIT(mb + s * 8, NTHREADS);        // full[s]: per-thread cp arrivals
            MBAR_INIT(mb + 24 + s * 8, NWARPS);     // free[s]: per-warp arrivals
        }
    }
    if (tid < NT) {
        ((float*)(smem + OFF_SCALE))[tid] = g_scale[oc0 + tid];
        ((float*)(smem + OFF_BIAS))[tid]  = g_bias[oc0 + tid];
    }
    __syncthreads();   // init visibility; only CTA-wide barrier

    // ---- loader assignment -------------------------------------------------
    // A: 4 threads per 128B pixel row, 2 segs each (hi and lo) -> 4 cp16
    const int arow  = tid >> 2;                // 0..127
    const int asegb = (tid & 3) * 2;           // seg start (of 8)
    // B: 4 threads per 128B oc row, 2 segs each -> 2 cp16
    const int brow  = tid >> 2;                // 0..127
    const int bsegb = (tid & 3) * 2;

    const int pg   = p0 + arow;
    const int nimg = pg / HWSQ;
    const int rem  = pg - nimg * HWSQ;
    const int oh   = rem / HW;
    const int ow   = rem - oh * HW;
    const __half* xhi_n = g_x_hi + (size_t)nimg * (HWP * HWP * IN_CH);
    const __half* xlo_n = g_x_lo + (size_t)nimg * (HWP * HWP * IN_CH);
    uint32_t dA[2], dB[2];
    #pragma unroll
    for (int j = 0; j < 2; ++j) {
        dA[j] = sw128((uint32_t)(arow * 128 + (asegb + j) * 16));
        dB[j] = sw128((uint32_t)(brow * 128 + (bsegb + j) * 16));
    }

    auto issue_loads = [&](int kc, int st) {
        const int rs = kc >> 1, half = kc & 1;
        const int r = rs / 3, sc = rs - r * 3;
        const size_t aoff = (((size_t)(oh + r) * HWP) + (ow + sc)) * IN_CH
                            + half * 64 + asegb * 8;
        const size_t boff = ((size_t)(oc0 + brow) * 9 + rs) * 128
                            + half * 64 + bsegb * 8;
        const uint32_t s0 = sb + st * STG_BYTES;
        #pragma unroll
        for (int j = 0; j < 2; ++j) {
            cp16(s0 + SOFF_AHI + dA[j], xhi_n + aoff + j * 8);
            cp16(s0 + SOFF_ALO + dA[j], xlo_n + aoff + j * 8);
            cp16(s0 + SOFF_B + dB[j], g_w + boff + j * 8);
        }
    };

    float acc[2][4][4];
    #pragma unroll
    for (int f = 0; f < 2; ++f)
        #pragma unroll
        for (int g = 0; g < 4; ++g)
            #pragma unroll
            for (int e = 0; e < 4; ++e) acc[f][g][e] = 0.0f;

    // ldmatrix lane mapping
    const int li = lid >> 3;
    const int lj = lid & 7;
    const int a_row = warpM * 32 + (li & 1) * 8 + lj;
    const int a_kof = (li >> 1) * 8;
    const int b_row = warpN * 32 + (li >> 1) * 8 + lj;
    const int b_kof = (li & 1) * 8;

    // double-buffered fragments
    uint32_t Ahi[2][2][4], Alo[2][2][4], Bf[2][4][2];

    auto load_frags = [&](uint32_t s0, int ks, int bu) {
        #pragma unroll
        for (int f = 0; f < 2; ++f) {
            uint32_t off = sw128((uint32_t)((a_row + f * 16) * 128 +
                                            (ks * 16 + a_kof) * 2));
            ldsm4(Ahi[bu][f], s0 + SOFF_AHI + off);
            ldsm4(Alo[bu][f], s0 + SOFF_ALO + off);
        }
        #pragma unroll
        for (int h = 0; h < 2; ++h) {
            uint32_t off = sw128((uint32_t)((b_row + h * 16) * 128 +
                                            (ks * 16 + b_kof) * 2));
            uint32_t t[4];
            ldsm4(t, s0 + SOFF_B + off);
            Bf[bu][h*2+0][0] = t[0]; Bf[bu][h*2+0][1] = t[1];
            Bf[bu][h*2+1][0] = t[2]; Bf[bu][h*2+1][1] = t[3];
        }
    };

    auto mma_block = [&](int bu) {
        #pragma unroll
        for (int f = 0; f < 2; ++f)
            #pragma unroll
            for (int g = 0; g < 4; ++g) {
                mma16816(acc[f][g], Ahi[bu][f], Bf[bu][g]);
                mma16816(acc[f][g], Alo[bu][f], Bf[bu][g]);
            }
    };

    // ---- pipeline prologue: fill stages 0 and 1; preload chunk0 ks0 frags --
    issue_loads(0, 0); CP_MBAR_ARRIVE(mb + 0);
    issue_loads(1, 1); CP_MBAR_ARRIVE(mb + 8);
    MBAR_WAIT(mb + 0, 0);
    load_frags(sb, 0, 0);

    for (int kc = 0; kc < NCHUNK; ++kc) {
        const int rnd = kc / 3;
        const int s   = kc - rnd * 3;
        const uint32_t s0 = sb + s * STG_BYTES;

        // ks = 0
        load_frags(s0, 1, 1);
        mma_block(0);
        // ks = 1
        load_frags(s0, 2, 0);
        mma_block(1);
        // ks = 2: last stage-s ldsm -> release stage early (warp-counted)
        load_frags(s0, 3, 1);
        if (lid == 0) MBAR_ARRIVE(mb + 24 + s * 8);
        mma_block(0);
        // ks = 3: cross-chunk prefetch (next chunk's ks0 from next stage)
        if (kc + 1 < NCHUNK) {
            const int rn1 = (kc + 1) / 3;
            const int sn1 = (kc + 1) - rn1 * 3;
            MBAR_WAIT(mb + sn1 * 8, rn1 & 1);            // usually already fired
            load_frags(sb + sn1 * STG_BYTES, 0, 0);
        }
        mma_block(1);

        // refill: stage (kc+2)%3 with chunk kc+2
        const int kn = kc + 2;
        if (kn < NCHUNK) {
            const int rn = kn / 3;
            const int sn = kn - rn * 3;
            if (kn >= STAGES)                  // stage sn last released in chunk kn-3
                MBAR_WAIT(mb + 24 + sn * 8, (rn - 1) & 1);
            issue_loads(kn, sn);
            CP_MBAR_ARRIVE(mb + sn * 8);
        }
    }

    // ---- epilogue: BN + ReLU6 + stores ------------------------------------
    const float* ss = (const float*)(smem + OFF_SCALE);
    const float* bb = (const float*)(smem + OFF_BIAS);

    #pragma unroll
    for (int f = 0; f < 2; ++f) {
        int p1 = p0 + warpM * 32 + f * 16 + (lid >> 2);
        int p2 = p1 + 8;
        int n1 = p1 / HWSQ, r1 = p1 - n1 * HWSQ;
        int n2 = p2 / HWSQ, r2 = p2 - n2 * HWSQ;
        float* o1 = out + (size_t)n1 * OUT_CH * HWSQ + r1;
        float* o2 = out + (size_t)n2 * OUT_CH * HWSQ + r2;
        #pragma unroll
        for (int g = 0; g < 4; ++g) {
            int cl = warpN * 32 + g * 8 + (lid & 3) * 2;
            int ocA = oc0 + cl, ocB = ocA + 1;
            float sA = ss[cl], bA = bb[cl];
            float sB = ss[cl + 1], bB = bb[cl + 1];
            float v0 = fminf(fmaxf(acc[f][g][0] * sA + bA, 0.0f), 6.0f);
            float v1 = fminf(fmaxf(acc[f][g][1] * sB + bB, 0.0f), 6.0f);
            float v2 = fminf(fmaxf(acc[f][g][2] * sA + bA, 0.0f), 6.0f);
            float v3 = fminf(fmaxf(acc[f][g][3] * sB + bB, 0.0f), 6.0f);
            o1[(size_t)ocA * HWSQ] = v0;
            o1[(size_t)ocB * HWSQ] = v1;
            o2[(size_t)ocA * HWSQ] = v2;
            o2[(size_t)ocB * HWSQ] = v3;
        }
    }
}

// ---------------------------------------------------------------------------
// Launch
// ---------------------------------------------------------------------------
extern "C" void kernel_launch(void* const* d_in, const int* in_sizes, int n_in,
                              void* d_out, int out_size) {
    const float* x     = (const float*)d_in[0];
    const float* phase = (const float*)d_in[1];
    const float* gamma = (const float*)d_in[2];
    const float* beta  = (const float*)d_in[3];
    const float* rmean = (const float*)d_in[4];
    const float* rvar  = (const float*)d_in[5];
    float* out = (float*)d_out;

    cudaFuncSetAttribute(conv_kernel,
                         cudaFuncAttributeMaxDynamicSharedMemorySize, SMEM_TOTAL);

    prep_kernel<<<(OUT_CH * KTOT + 255) / 256, 256>>>(phase, gamma, beta, rmean, rvar);
    dim3 xg(64, HW);
    xprep_kernel<<<xg, 256>>>(x);

    dim3 grid(OUT_CH / NT, PIXTOT / MT);   // (2, 1568): oc-major for A-tile L2 reuse
    conv_kernel<<<grid, NTHREADS, SMEM_TOTAL>>>(out);
}

// round 17
// speedup vs baseline: 2.0674x; 1.4329x over previous
#include <cuda_runtime.h>
#include <cuda_fp16.h>
#include <stdint.h>

// ---------------------------------------------------------------------------
// Constants
// ---------------------------------------------------------------------------
#define MRR_A 0.987f
#define MRR_R 0.99f

#define OUT_CH 256
#define IN_CH  128
#define HW     56
#define HWP    58          // padded spatial
#define HWSQ   3136
#define KTOT   1152
#define PIXTOT 200704

#define KC      64
#define NCHUNK  18         // 9 (r,s) positions x 2 channel-halves
#define MT      128
#define NT      128
#define STAGES  3
#define NTHREADS 512       // 16 warps, grid 4x4, warp tile 32x32
#define NWARPS  16

// per-stage smem layout (bytes): A + B (single fp16 each)
#define STG_BYTES 32768
#define SOFF_A    0        // 128 rows x 128B = 16KB
#define SOFF_B    16384    // 128 rows x 128B = 16KB
#define OFF_SCALE (STAGES * STG_BYTES)          // 98304
#define OFF_BIAS  (OFF_SCALE + 512)
#define OFF_MBAR  (OFF_BIAS + 512)              // full[0..2] @ +0,8,16; free[0..2] @ +24,32,40
#define SMEM_TOTAL (OFF_MBAR + 64)              // ~99.4KB

// ---------------------------------------------------------------------------
// Device-global scratch (zero-initialized -> halo stays zero forever)
// ---------------------------------------------------------------------------
__device__ __align__(256) __half g_x[64 * HWP * HWP * IN_CH];
__device__ __align__(256) __half g_w[OUT_CH * KTOT];   // [oc][rs][c], fp16
__device__ float g_scale[OUT_CH];
__device__ float g_bias[OUT_CH];

// ---------------------------------------------------------------------------
// Helpers
// ---------------------------------------------------------------------------
__device__ __forceinline__ uint32_t smem_u32(const void* p) {
    uint32_t a;
    asm("{ .reg .u64 t; cvta.to.shared.u64 t, %1; cvt.u32.u64 %0, t; }" : "=r"(a) : "l"(p));
    return a;
}
__device__ __forceinline__ uint32_t sw128(uint32_t off) {
    return off ^ ((off >> 3) & 0x70);
}
__device__ __forceinline__ void cp16(uint32_t dst, const __half* src) {
    asm volatile("cp.async.cg.shared.global [%0], [%1], 16;"
                 :: "r"(dst), "l"(__cvta_generic_to_global(src)));
}

#define MBAR_INIT(a, c) \
    asm volatile("mbarrier.init.shared.b64 [%0], %1;" :: "r"(a), "r"(c) : "memory")
#define CP_MBAR_ARRIVE(a) \
    asm volatile("cp.async.mbarrier.arrive.noinc.shared.b64 [%0];" :: "r"(a) : "memory")
#define MBAR_ARRIVE(a) \
    asm volatile("mbarrier.arrive.shared.b64 _, [%0];" :: "r"(a) : "memory")

#define MBAR_WAIT(mbar, parity) do {                                              \
    uint32_t _m = (uint32_t)(mbar);                                               \
    uint32_t _p = (uint32_t)(parity);                                             \
    uint32_t _done;                                                               \
    asm volatile(                                                                 \
        "{\n\t.reg .pred p;\n\t"                                                  \
        "mbarrier.try_wait.parity.acquire.cta.shared::cta.b64 p, [%1], %2;\n\t"   \
        "selp.b32 %0, 1, 0, p;\n\t}"                                              \
        : "=r"(_done) : "r"(_m), "r"(_p) : "memory");                             \
    if (!_done) {                                                                 \
        asm volatile(                                                             \
            "{\n\t.reg .pred P1;\n\t"                                             \
            "WAIT_LOOP_%=:\n\t"                                                   \
            "mbarrier.try_wait.parity.acquire.cta.shared::cta.b64 P1, [%0], %1, 0x989680;\n\t" \
            "@P1 bra.uni WAIT_DONE_%=;\n\t"                                       \
            "bra.uni WAIT_LOOP_%=;\n\t"                                           \
            "WAIT_DONE_%=:\n\t}"                                                  \
            :: "r"(_m), "r"(_p) : "memory");                                      \
    }                                                                             \
} while (0)

__device__ __forceinline__ void ldsm4(uint32_t* r, uint32_t addr) {
    asm volatile("ldmatrix.sync.aligned.m8n8.x4.shared.b16 {%0,%1,%2,%3}, [%4];"
                 : "=r"(r[0]), "=r"(r[1]), "=r"(r[2]), "=r"(r[3]) : "r"(addr));
}
__device__ __forceinline__ void mma16816(float* d, const uint32_t* a, const uint32_t* b) {
    asm volatile(
        "mma.sync.aligned.m16n8k16.row.col.f32.f16.f16.f32 "
        "{%0,%1,%2,%3}, {%4,%5,%6,%7}, {%8,%9}, {%0,%1,%2,%3};"
        : "+f"(d[0]), "+f"(d[1]), "+f"(d[2]), "+f"(d[3])
        : "r"(a[0]), "r"(a[1]), "r"(a[2]), "r"(a[3]), "r"(b[0]), "r"(b[1]));
}

__device__ __forceinline__ float mrr_tr(float phi) {
    float cc = cosf(phi);
    float ar = MRR_A * MRR_R;
    float num = MRR_A * MRR_A - 2.0f * ar * cc + MRR_R * MRR_R;
    float den = 1.0f - 2.0f * ar * cc + ar * ar;
    return num / den;
}

// ---------------------------------------------------------------------------
// Kernel 1: weights — MRR phase -> fp16 in [oc][rs][c] order + BN fold
// ---------------------------------------------------------------------------
__global__ void prep_kernel(const float* __restrict__ phase,
                            const float* __restrict__ gamma,
                            const float* __restrict__ beta,
                            const float* __restrict__ rmean,
                            const float* __restrict__ rvar) {
    int idx = blockIdx.x * 256 + threadIdx.x;
    if (idx < OUT_CH * KTOT) {
        int oc  = idx / KTOT;
        int kp  = idx - oc * KTOT;     // rs*128 + c
        int rs  = kp >> 7;
        int c   = kp & 127;
        int korig = c * 9 + rs;        // original (c,r,s) K order used by the blocks
        int gy = oc >> 3, i = oc & 7;
        int gx = korig >> 3, j = korig & 7;
        float tr = mrr_tr(phase[((gy * 144 + gx) * 8 + i) * 8 + j]);
        g_w[idx] = __float2half(tr);
    }
    if (idx < OUT_CH) {
        float inv = gamma[idx] * rsqrtf(rvar[idx] + 1e-5f);
        g_scale[idx] = inv;
        g_bias[idx]  = beta[idx] - rmean[idx] * inv;
    }
}

// ---------------------------------------------------------------------------
// Kernel 2: x NCHW fp32 -> padded NHWC fp16 (smem transpose)
// ---------------------------------------------------------------------------
__global__ void __launch_bounds__(256)
xprep_kernel(const float* __restrict__ x) {
    __shared__ float tile[IN_CH][HW + 1];
    const int n = blockIdx.x, h = blockIdx.y;
    const int tid = threadIdx.x;
    const float* xb = x + (size_t)n * IN_CH * HWSQ + h * HW;
    #pragma unroll 4
    for (int i = tid; i < IN_CH * HW; i += 256) {
        int c = i / HW, w = i - c * HW;
        tile[c][w] = xb[(size_t)c * HWSQ + w];
    }
    __syncthreads();
    const size_t obase = (((size_t)n * HWP + h + 1) * HWP + 1) * IN_CH;
    #pragma unroll 4
    for (int i = tid; i < HW * IN_CH; i += 256) {
        int w = i >> 7, c = i & 127;
        g_x[obase + (size_t)w * IN_CH + c] = __float2half(tile[c][w]);
    }
}

// ---------------------------------------------------------------------------
// Kernel 3: implicit-GEMM conv, mbarrier 3-stage pipeline, fp16 1-pass mma
//   512 threads, warp grid 4x4, warp tile 32x32, cross-chunk fragment pipeline
// ---------------------------------------------------------------------------
__global__ void __launch_bounds__(NTHREADS, 1)
conv_kernel(float* __restrict__ out) {
    extern __shared__ char smem[];
    const uint32_t sb = smem_u32(smem);
    const uint32_t mb = sb + OFF_MBAR;
    const int tid = threadIdx.x;
    const int wid = tid >> 5;
    const int lid = tid & 31;
    const int p0  = blockIdx.y * MT;   // pixel tile base
    const int oc0 = blockIdx.x * NT;   // oc tile base (adjacent bids share A in L2)

    const int warpM = wid >> 2;        // 0..3 -> 32-pixel band
    const int warpN = wid & 3;         // 0..3 -> 32-oc band

    if (tid == 0) {
        #pragma unroll
        for (int s = 0; s < STAGES; ++s) {
            MBAR_INIT(mb + s * 8, NTHREADS);        // full[s]: per-thread cp arrivals
            MBAR_INIT(mb + 24 + s * 8, NWARPS);     // free[s]: per-warp arrivals
        }
    }
    if (tid < NT) {
        ((float*)(smem + OFF_SCALE))[tid] = g_scale[oc0 + tid];
        ((float*)(smem + OFF_BIAS))[tid]  = g_bias[oc0 + tid];
    }
    __syncthreads();   // init visibility; only CTA-wide barrier

    // ---- loader assignment -------------------------------------------------
    // A: 4 threads per 128B pixel row, 2 segs each -> 2 cp16
    const int arow  = tid >> 2;                // 0..127
    const int asegb = (tid & 3) * 2;           // seg start (of 8)
    // B: 4 threads per 128B oc row, 2 segs each -> 2 cp16
    const int brow  = tid >> 2;                // 0..127
    const int bsegb = (tid & 3) * 2;

    const int pg   = p0 + arow;
    const int nimg = pg / HWSQ;
    const int rem  = pg - nimg * HWSQ;
    const int oh   = rem / HW;
    const int ow   = rem - oh * HW;
    const __half* x_n = g_x + (size_t)nimg * (HWP * HWP * IN_CH);
    uint32_t dA[2], dB[2];
    #pragma unroll
    for (int j = 0; j < 2; ++j) {
        dA[j] = sw128((uint32_t)(arow * 128 + (asegb + j) * 16));
        dB[j] = sw128((uint32_t)(brow * 128 + (bsegb + j) * 16));
    }

    auto issue_loads = [&](int kc, int st) {
        const int rs = kc >> 1, half = kc & 1;
        const int r = rs / 3, sc = rs - r * 3;
        const size_t aoff = (((size_t)(oh + r) * HWP) + (ow + sc)) * IN_CH
                            + half * 64 + asegb * 8;
        const size_t boff = ((size_t)(oc0 + brow) * 9 + rs) * 128
                            + half * 64 + bsegb * 8;
        const uint32_t s0 = sb + st * STG_BYTES;
        #pragma unroll
        for (int j = 0; j < 2; ++j) {
            cp16(s0 + SOFF_A + dA[j], x_n + aoff + j * 8);
            cp16(s0 + SOFF_B + dB[j], g_w + boff + j * 8);
        }
    };

    float acc[2][4][4];
    #pragma unroll
    for (int f = 0; f < 2; ++f)
        #pragma unroll
        for (int g = 0; g < 4; ++g)
            #pragma unroll
            for (int e = 0; e < 4; ++e) acc[f][g][e] = 0.0f;

    // ldmatrix lane mapping
    const int li = lid >> 3;
    const int lj = lid & 7;
    const int a_row = warpM * 32 + (li & 1) * 8 + lj;
    const int a_kof = (li >> 1) * 8;
    const int b_row = warpN * 32 + (li >> 1) * 8 + lj;
    const int b_kof = (li & 1) * 8;

    // double-buffered fragments
    uint32_t Af[2][2][4], Bf[2][4][2];

    auto load_frags = [&](uint32_t s0, int ks, int bu) {
        #pragma unroll
        for (int f = 0; f < 2; ++f) {
            uint32_t off = sw128((uint32_t)((a_row + f * 16) * 128 +
                                            (ks * 16 + a_kof) * 2));
            ldsm4(Af[bu][f], s0 + SOFF_A + off);
        }
        #pragma unroll
        for (int h = 0; h < 2; ++h) {
            uint32_t off = sw128((uint32_t)((b_row + h * 16) * 128 +
                                            (ks * 16 + b_kof) * 2));
            uint32_t t[4];
            ldsm4(t, s0 + SOFF_B + off);
            Bf[bu][h*2+0][0] = t[0]; Bf[bu][h*2+0][1] = t[1];
            Bf[bu][h*2+1][0] = t[2]; Bf[bu][h*2+1][1] = t[3];
        }
    };

    auto mma_block = [&](int bu) {
        #pragma unroll
        for (int f = 0; f < 2; ++f)
            #pragma unroll
            for (int g = 0; g < 4; ++g)
                mma16816(acc[f][g], Af[bu][f], Bf[bu][g]);
    };

    // ---- pipeline prologue: fill stages 0 and 1; preload chunk0 ks0 frags --
    issue_loads(0, 0); CP_MBAR_ARRIVE(mb + 0);
    issue_loads(1, 1); CP_MBAR_ARRIVE(mb + 8);
    MBAR_WAIT(mb + 0, 0);
    load_frags(sb, 0, 0);

    for (int kc = 0; kc < NCHUNK; ++kc) {
        const int rnd = kc / 3;
        const int s   = kc - rnd * 3;
        const uint32_t s0 = sb + s * STG_BYTES;

        // ks = 0
        load_frags(s0, 1, 1);
        mma_block(0);
        // ks = 1
        load_frags(s0, 2, 0);
        mma_block(1);
        // ks = 2: last stage-s ldsm -> release stage early (warp-counted)
        load_frags(s0, 3, 1);
        if (lid == 0) MBAR_ARRIVE(mb + 24 + s * 8);
        mma_block(0);
        // ks = 3: cross-chunk prefetch (next chunk's ks0 from next stage)
        if (kc + 1 < NCHUNK) {
            const int rn1 = (kc + 1) / 3;
            const int sn1 = (kc + 1) - rn1 * 3;
            MBAR_WAIT(mb + sn1 * 8, rn1 & 1);            // usually already fired
            load_frags(sb + sn1 * STG_BYTES, 0, 0);
        }
        mma_block(1);

        // refill: stage (kc+2)%3 with chunk kc+2
        const int kn = kc + 2;
        if (kn < NCHUNK) {
            const int rn = kn / 3;
            const int sn = kn - rn * 3;
            if (kn >= STAGES)                  // stage sn last released in chunk kn-3
                MBAR_WAIT(mb + 24 + sn * 8, (rn - 1) & 1);
            issue_loads(kn, sn);
            CP_MBAR_ARRIVE(mb + sn * 8);
        }
    }

    // ---- epilogue: BN + ReLU6 + stores ------------------------------------
    const float* ss = (const float*)(smem + OFF_SCALE);
    const float* bb = (const float*)(smem + OFF_BIAS);

    #pragma unroll
    for (int f = 0; f < 2; ++f) {
        int p1 = p0 + warpM * 32 + f * 16 + (lid >> 2);
        int p2 = p1 + 8;
        int n1 = p1 / HWSQ, r1 = p1 - n1 * HWSQ;
        int n2 = p2 / HWSQ, r2 = p2 - n2 * HWSQ;
        float* o1 = out + (size_t)n1 * OUT_CH * HWSQ + r1;
        float* o2 = out + (size_t)n2 * OUT_CH * HWSQ + r2;
        #pragma unroll
        for (int g = 0; g < 4; ++g) {
            int cl = warpN * 32 + g * 8 + (lid & 3) * 2;
            int ocA = oc0 + cl, ocB = ocA + 1;
            float sA = ss[cl], bA = bb[cl];
            float sB = ss[cl + 1], bB = bb[cl + 1];
            float v0 = fminf(fmaxf(acc[f][g][0] * sA + bA, 0.0f), 6.0f);
            float v1 = fminf(fmaxf(acc[f][g][1] * sB + bB, 0.0f), 6.0f);
            float v2 = fminf(fmaxf(acc[f][g][2] * sA + bA, 0.0f), 6.0f);
            float v3 = fminf(fmaxf(acc[f][g][3] * sB + bB, 0.0f), 6.0f);
            o1[(size_t)ocA * HWSQ] = v0;
            o1[(size_t)ocB * HWSQ] = v1;
            o2[(size_t)ocA * HWSQ] = v2;
            o2[(size_t)ocB * HWSQ] = v3;
        }
    }
}

// ---------------------------------------------------------------------------
// Launch
// ---------------------------------------------------------------------------
extern "C" void kernel_launch(void* const* d_in, const int* in_sizes, int n_in,
                              void* d_out, int out_size) {
    const float* x     = (const float*)d_in[0];
    const float* phase = (const float*)d_in[1];
    const float* gamma = (const float*)d_in[2];
    const float* beta  = (const float*)d_in[3];
    const float* rmean = (const float*)d_in[4];
    const float* rvar  = (const float*)d_in[5];
    float* out = (float*)d_out;

    cudaFuncSetAttribute(conv_kernel,
                         cudaFuncAttributeMaxDynamicSharedMemorySize, SMEM_TOTAL);

    prep_kernel<<<(OUT_CH * KTOT + 255) / 256, 256>>>(phase, gamma, beta, rmean, rvar);
    dim3 xg(64, HW);
    xprep_kernel<<<xg, 256>>>(x);

    dim3 grid(OUT_CH / NT, PIXTOT / MT);   // (2, 1568): oc-major for A-tile L2 reuse
    conv_kernel<<<grid, NTHREADS, SMEM_TOTAL>>>(out);
}